// round 15
// baseline (speedup 1.0000x reference)
#include <cuda_runtime.h>
#include <cuda_fp16.h>

#define NN 50000
#define NEMAX 1000000
#define NB 196          // ceil(NN/256)

// ---------------- scratch ----------------
__device__ __align__(256) float g_work[2 * NN];                 // [nsrc | ndst]
__device__ __align__(256) __half g_half[112 * NN];              // [y1 64NN | p2 32NN | p3 16NN]
// ints: [ideg NN | odeg NN | rowp NN+1 (+3 pad) | cur NN | csr NEMAX] ; csr 16B-aligned
__device__ __align__(256) int g_int[4 * NN + 4 + NEMAX];
__device__ __align__(256) unsigned long long g_status[256];     // lookback state (zero-init)

#define OFF_NSRC 0
#define OFF_NDST (NN)

#define HOFF_Y1 0
#define HOFF_P2 (64 * NN)
#define HOFF_P3 (96 * NN)

#define IOFF_IDEG 0
#define IOFF_ODEG (NN)
#define IOFF_ROWP (2 * NN)
#define IOFF_CUR  (3 * NN + 4)
#define IOFF_CSR  (4 * NN + 4)

// ---------------- degree ----------------

__global__ void k_deg(const int* __restrict__ src, const int* __restrict__ dst, int E) {
    int e = (blockIdx.x * blockDim.x + threadIdx.x) * 4;
    if (e + 3 < E) {
        int4 s = __ldg((const int4*)(src + e));
        int4 d = __ldg((const int4*)(dst + e));
        atomicAdd(&g_int[IOFF_ODEG + s.x], 1);
        atomicAdd(&g_int[IOFF_ODEG + s.y], 1);
        atomicAdd(&g_int[IOFF_ODEG + s.z], 1);
        atomicAdd(&g_int[IOFF_ODEG + s.w], 1);
        atomicAdd(&g_int[IOFF_IDEG + d.x], 1);
        atomicAdd(&g_int[IOFF_IDEG + d.y], 1);
        atomicAdd(&g_int[IOFF_IDEG + d.z], 1);
        atomicAdd(&g_int[IOFF_IDEG + d.w], 1);
    } else {
        for (int i = e; i < E; i++) {
            atomicAdd(&g_int[IOFF_ODEG + __ldg(src + i)], 1);
            atomicAdd(&g_int[IOFF_IDEG + __ldg(dst + i)], 1);
        }
    }
}

// ---------------- fused: norms + y1 scale + single-pass rowptr scan ------------

__global__ void k_scan_norm(const float* __restrict__ x) {
    __shared__ int sh[256];
    int t = threadIdx.x;
    int bid = blockIdx.x;
    int i = bid * 256 + t;

    int idv = 0, odv = 0;
    if (i < NN) {
        idv = g_int[IOFF_IDEG + i];
        odv = g_int[IOFF_ODEG + i];
    }
    float ns = rsqrtf(fmaxf((float)odv, 1.0f));
    float nd = rsqrtf(fmaxf((float)idv, 1.0f));
    if (i < NN) {
        g_work[OFF_NSRC + i] = ns;
        g_work[OFF_NDST + i] = nd;
    }

    sh[t] = idv;
    __syncthreads();
    for (int o = 1; o < 256; o <<= 1) {
        int v = (t >= o) ? sh[t - o] : 0;
        __syncthreads();
        sh[t] += v;
        __syncthreads();
    }
    int incl = sh[t];
    int total = sh[255];

    if (t == 0)
        atomicExch(&g_status[bid], (1ULL << 32) | (unsigned long long)(unsigned)total);

    if (i < NN) {
        const float4* px = (const float4*)(x + (long)i * 64);
        uint4* py = (uint4*)(g_half + HOFF_Y1) + i * 8;
#pragma unroll
        for (int q = 0; q < 8; q++) {
            float4 a = __ldg(px + q * 2);
            float4 b = __ldg(px + q * 2 + 1);
            __half2 h0 = __floats2half2_rn(a.x * ns, a.y * ns);
            __half2 h1 = __floats2half2_rn(a.z * ns, a.w * ns);
            __half2 h2 = __floats2half2_rn(b.x * ns, b.y * ns);
            __half2 h3 = __floats2half2_rn(b.z * ns, b.w * ns);
            uint4 u;
            u.x = *(unsigned*)&h0; u.y = *(unsigned*)&h1;
            u.z = *(unsigned*)&h2; u.w = *(unsigned*)&h3;
            py[q] = u;
        }
    }

    int myagg = 0;
    if (t < bid) {
        unsigned long long v;
        do { v = atomicOr(&g_status[t], 0ULL); } while ((v >> 32) == 0);
        myagg = (int)(v & 0xffffffffULL);
    }
    __syncthreads();
    sh[t] = myagg;
    __syncthreads();
    for (int o = 128; o > 0; o >>= 1) {
        if (t < o) sh[t] += sh[t + o];
        __syncthreads();
    }
    int blockpre = sh[0];

    int excl = blockpre + incl - idv;
    if (i < NN) {
        g_int[IOFF_ROWP + i] = excl;
        g_int[IOFF_CUR + i] = excl;
    }
    if (i == NN - 1) g_int[IOFF_ROWP + NN] = excl + idv;
}

__global__ void k_fill(const int* __restrict__ src, const int* __restrict__ dst, int E) {
    int e = (blockIdx.x * blockDim.x + threadIdx.x) * 4;
    if (e + 3 < E) {
        int4 s = __ldg((const int4*)(src + e));
        int4 d = __ldg((const int4*)(dst + e));
        g_int[IOFF_CSR + atomicAdd(&g_int[IOFF_CUR + d.x], 1)] = s.x;
        g_int[IOFF_CSR + atomicAdd(&g_int[IOFF_CUR + d.y], 1)] = s.y;
        g_int[IOFF_CSR + atomicAdd(&g_int[IOFF_CUR + d.z], 1)] = s.z;
        g_int[IOFF_CSR + atomicAdd(&g_int[IOFF_CUR + d.w], 1)] = s.w;
    } else {
        for (int i = e; i < E; i++) {
            int pos = atomicAdd(&g_int[IOFF_CUR + __ldg(dst + i)], 1);
            g_int[IOFF_CSR + pos] = __ldg(src + i);
        }
    }
}

// ---------------- packed fp32x2 accumulation helpers ----------------

__device__ __forceinline__ void acc_h2(unsigned long long& a, __half2 h) {
    float2 f = __half22float2(h);
    unsigned long long p;
    asm("mov.b64 %0, {%1, %2};" : "=l"(p) : "f"(f.x), "f"(f.y));
    asm("add.rn.f32x2 %0, %0, %1;" : "+l"(a) : "l"(p));
}

__device__ __forceinline__ void acc_pair(unsigned long long acc[4], uint4 a, uint4 b) {
    __half2 s0 = __hadd2(*(__half2*)&a.x, *(__half2*)&b.x);
    __half2 s1 = __hadd2(*(__half2*)&a.y, *(__half2*)&b.y);
    __half2 s2 = __hadd2(*(__half2*)&a.z, *(__half2*)&b.z);
    __half2 s3 = __hadd2(*(__half2*)&a.w, *(__half2*)&b.w);
    acc_h2(acc[0], s0); acc_h2(acc[1], s1); acc_h2(acc[2], s2); acc_h2(acc[3], s3);
}

__device__ __forceinline__ void acc_one(unsigned long long acc[4], uint4 u) {
    acc_h2(acc[0], *(__half2*)&u.x);
    acc_h2(acc[1], *(__half2*)&u.y);
    acc_h2(acc[2], *(__half2*)&u.z);
    acc_h2(acc[3], *(__half2*)&u.w);
}

__device__ __forceinline__ void unpack8(const unsigned long long acc[4], float o[8]) {
#pragma unroll
    for (int k = 0; k < 4; k++)
        asm("mov.b64 {%0, %1}, %2;" : "=f"(o[2 * k]), "=f"(o[2 * k + 1]) : "l"(acc[k]));
}

// gather: C lanes per node, 1 chunk per lane; int4 idx broadcast with
// software-pipelined index prefetch.
template <int C>
__device__ __forceinline__ void gather_row(unsigned long long acc[4], int n, int c,
                                           const uint4* __restrict__ msg) {
    int beg = __ldg(&g_int[IOFF_ROWP + n]);
    int end = __ldg(&g_int[IOFF_ROWP + n + 1]);
    int i = beg;
    while (i < end && (i & 3)) {
        acc_one(acc, msg[__ldg(&g_int[IOFF_CSR + i]) * C + c]);
        i++;
    }
    if (i + 7 < end) {
        int4 sa = __ldg((const int4*)&g_int[IOFF_CSR + i]);
        int4 sb = __ldg((const int4*)&g_int[IOFF_CSR + i + 4]);
        for (; i + 15 < end; i += 8) {
            int4 na = __ldg((const int4*)&g_int[IOFF_CSR + i + 8]);
            int4 nb = __ldg((const int4*)&g_int[IOFF_CSR + i + 12]);
            uint4 u0 = msg[sa.x * C + c];
            uint4 u1 = msg[sa.y * C + c];
            uint4 u2 = msg[sa.z * C + c];
            uint4 u3 = msg[sa.w * C + c];
            uint4 u4 = msg[sb.x * C + c];
            uint4 u5 = msg[sb.y * C + c];
            uint4 u6 = msg[sb.z * C + c];
            uint4 u7 = msg[sb.w * C + c];
            acc_pair(acc, u0, u1); acc_pair(acc, u2, u3);
            acc_pair(acc, u4, u5); acc_pair(acc, u6, u7);
            sa = na; sb = nb;
        }
        {
            uint4 u0 = msg[sa.x * C + c];
            uint4 u1 = msg[sa.y * C + c];
            uint4 u2 = msg[sa.z * C + c];
            uint4 u3 = msg[sa.w * C + c];
            uint4 u4 = msg[sb.x * C + c];
            uint4 u5 = msg[sb.y * C + c];
            uint4 u6 = msg[sb.z * C + c];
            uint4 u7 = msg[sb.w * C + c];
            acc_pair(acc, u0, u1); acc_pair(acc, u2, u3);
            acc_pair(acc, u4, u5); acc_pair(acc, u6, u7);
            i += 8;
        }
    }
    if (i + 3 < end) {
        int4 sa = __ldg((const int4*)&g_int[IOFF_CSR + i]);
        uint4 u0 = msg[sa.x * C + c];
        uint4 u1 = msg[sa.y * C + c];
        uint4 u2 = msg[sa.z * C + c];
        uint4 u3 = msg[sa.w * C + c];
        acc_pair(acc, u0, u1); acc_pair(acc, u2, u3);
        i += 4;
    }
    for (; i < end; i++)
        acc_one(acc, msg[__ldg(&g_int[IOFF_CSR + i]) * C + c]);
}

// layer-1 gather: 4 lanes/node, 2 consecutive chunks per lane, idx prefetch.
__device__ __forceinline__ void gather_row1(unsigned long long accA[4],
                                            unsigned long long accB[4],
                                            int n, int lane,
                                            const uint4* __restrict__ msg) {
    int beg = __ldg(&g_int[IOFF_ROWP + n]);
    int end = __ldg(&g_int[IOFF_ROWP + n + 1]);
    int i = beg;
    while (i < end && (i & 3)) {
        const uint4* m = msg + __ldg(&g_int[IOFF_CSR + i]) * 8 + lane * 2;
        acc_one(accA, m[0]);
        acc_one(accB, m[1]);
        i++;
    }
    if (i + 3 < end) {
        int4 sa = __ldg((const int4*)&g_int[IOFF_CSR + i]);
        for (; i + 7 < end; i += 4) {
            int4 na = __ldg((const int4*)&g_int[IOFF_CSR + i + 4]);
            const uint4* m0 = msg + sa.x * 8 + lane * 2;
            const uint4* m1 = msg + sa.y * 8 + lane * 2;
            const uint4* m2 = msg + sa.z * 8 + lane * 2;
            const uint4* m3 = msg + sa.w * 8 + lane * 2;
            uint4 a0 = m0[0], b0 = m0[1];
            uint4 a1 = m1[0], b1 = m1[1];
            uint4 a2 = m2[0], b2 = m2[1];
            uint4 a3 = m3[0], b3 = m3[1];
            acc_pair(accA, a0, a1); acc_pair(accB, b0, b1);
            acc_pair(accA, a2, a3); acc_pair(accB, b2, b3);
            sa = na;
        }
        {
            const uint4* m0 = msg + sa.x * 8 + lane * 2;
            const uint4* m1 = msg + sa.y * 8 + lane * 2;
            const uint4* m2 = msg + sa.z * 8 + lane * 2;
            const uint4* m3 = msg + sa.w * 8 + lane * 2;
            uint4 a0 = m0[0], b0 = m0[1];
            uint4 a1 = m1[0], b1 = m1[1];
            uint4 a2 = m2[0], b2 = m2[1];
            uint4 a3 = m3[0], b3 = m3[1];
            acc_pair(accA, a0, a1); acc_pair(accB, b0, b1);
            acc_pair(accA, a2, a3); acc_pair(accB, b2, b3);
            i += 4;
        }
    }
    for (; i < end; i++) {
        const uint4* m = msg + __ldg(&g_int[IOFF_CSR + i]) * 8 + lane * 2;
        acc_one(accA, m[0]);
        acc_one(accB, m[1]);
    }
}

// ---------------- fused layer 1: gather(y1) -> h1 -> p2(fp16) ----------------
// 256 thr, 64-node tiles. Gather: 4 lanes/node x 2 chunks.
// W1-MM: 4 nodes x 4 cols per thread. p2-MM: 2 nodes x 4 cols (all threads).
// launch_bounds(256,7): push regs to 36 for 7 blocks/SM occupancy.

__global__ void __launch_bounds__(256, 7)
k_L1(const float* __restrict__ W1, const float* __restrict__ b1,
     const float* __restrict__ W2) {
    __shared__ float sbuf[64][68];   // agg1, then reused for relu(h1)

    int t = threadIdx.x;
    {
        int lane = t & 3;
        int ln = t >> 2;             // 0..63
        int node = blockIdx.x * 64 + ln;
        unsigned long long accA[4] = {0ULL, 0ULL, 0ULL, 0ULL};
        unsigned long long accB[4] = {0ULL, 0ULL, 0ULL, 0ULL};
        float nd = 0.0f;
        if (node < NN) {
            gather_row1(accA, accB, node, lane, (const uint4*)(g_half + HOFF_Y1));
            nd = __ldg(&g_work[OFF_NDST + node]);
        }
        float a8[8];
        unpack8(accA, a8);
#pragma unroll
        for (int j = 0; j < 8; j++) sbuf[ln][lane * 16 + j] = a8[j] * nd;
        unpack8(accB, a8);
#pragma unroll
        for (int j = 0; j < 8; j++) sbuf[ln][lane * 16 + 8 + j] = a8[j] * nd;
    }
    __syncthreads();

    // W1-MM phase: cq = col chunk (4 cols of 64), q = node quad (4 nodes)
    int cq = t & 15;                 // 0..15
    int q = t >> 4;                  // 0..15
    int lnq = q * 4;

    float4 bb = __ldg((const float4*)(b1 + cq * 4));
    float h[4][4];
#pragma unroll
    for (int n = 0; n < 4; n++) {
        h[n][0] = bb.x; h[n][1] = bb.y; h[n][2] = bb.z; h[n][3] = bb.w;
    }
#pragma unroll 8
    for (int k = 0; k < 64; k++) {
        float4 w = __ldg((const float4*)(W1 + k * 64 + cq * 4));
        float a0 = sbuf[lnq + 0][k];
        float a1 = sbuf[lnq + 1][k];
        float a2 = sbuf[lnq + 2][k];
        float a3 = sbuf[lnq + 3][k];
        h[0][0] += a0 * w.x; h[0][1] += a0 * w.y; h[0][2] += a0 * w.z; h[0][3] += a0 * w.w;
        h[1][0] += a1 * w.x; h[1][1] += a1 * w.y; h[1][2] += a1 * w.z; h[1][3] += a1 * w.w;
        h[2][0] += a2 * w.x; h[2][1] += a2 * w.y; h[2][2] += a2 * w.z; h[2][3] += a2 * w.w;
        h[3][0] += a3 * w.x; h[3][1] += a3 * w.y; h[3][2] += a3 * w.z; h[3][3] += a3 * w.w;
    }
    __syncthreads();   // all reads of agg1 done -> reuse buffer
#pragma unroll
    for (int n = 0; n < 4; n++) {
#pragma unroll
        for (int j = 0; j < 4; j++)
            sbuf[lnq + n][cq * 4 + j] = fmaxf(h[n][j], 0.0f);
    }
    __syncthreads();

    // p2 = (h1 @ W2) * nsrc -> fp16 ; thread covers 4 cols x 2 nodes (all 256 thr)
    int c4 = t & 7;
    int pr = t >> 3;
    int ln0 = pr * 2, ln1 = pr * 2 + 1;
    int node0 = blockIdx.x * 64 + ln0;
    int node1 = node0 + 1;

    float p0[4] = {0.f, 0.f, 0.f, 0.f};
    float p1[4] = {0.f, 0.f, 0.f, 0.f};
#pragma unroll 8
    for (int k = 0; k < 64; k++) {
        float a0 = sbuf[ln0][k];
        float a1 = sbuf[ln1][k];
        float4 w = __ldg((const float4*)(W2 + k * 32 + c4 * 4));
        p0[0] += a0 * w.x; p0[1] += a0 * w.y; p0[2] += a0 * w.z; p0[3] += a0 * w.w;
        p1[0] += a1 * w.x; p1[1] += a1 * w.y; p1[2] += a1 * w.z; p1[3] += a1 * w.w;
    }
    if (node0 < NN) {
        float ns0 = __ldg(&g_work[OFF_NSRC + node0]);
        __half2 q0 = __floats2half2_rn(p0[0] * ns0, p0[1] * ns0);
        __half2 q1 = __floats2half2_rn(p0[2] * ns0, p0[3] * ns0);
        uint2 u;
        u.x = *(unsigned*)&q0; u.y = *(unsigned*)&q1;
        ((uint2*)(g_half + HOFF_P2))[node0 * 8 + c4] = u;
    }
    if (node1 < NN) {
        float ns1 = __ldg(&g_work[OFF_NSRC + node1]);
        __half2 q0 = __floats2half2_rn(p1[0] * ns1, p1[1] * ns1);
        __half2 q1 = __floats2half2_rn(p1[2] * ns1, p1[3] * ns1);
        uint2 u;
        u.x = *(unsigned*)&q0; u.y = *(unsigned*)&q1;
        ((uint2*)(g_half + HOFF_P2))[node1 * 8 + c4] = u;
    }
}

// ---------------- fused layer 2: gather(p2) -> embed(out) -> p3(fp16) --------
// 256 thr = 64 nodes x 4 chunks.

__global__ void __launch_bounds__(256, 6)
k_L2(const float* __restrict__ W3, const float* __restrict__ b2,
     float* __restrict__ out_embed) {
    __shared__ float semb[64][36];

    int t = threadIdx.x;
    int ln = t >> 2;
    int c = t & 3;
    int node = blockIdx.x * 64 + ln;
    bool valid = node < NN;

    unsigned long long acc64[4] = {0ULL, 0ULL, 0ULL, 0ULL};
    float nd = 0.0f, ns = 0.0f;
    if (valid) {
        gather_row<4>(acc64, node, c, (const uint4*)(g_half + HOFF_P2));
        nd = __ldg(&g_work[OFF_NDST + node]);
        ns = __ldg(&g_work[OFF_NSRC + node]);
    }
    float acc[8];
    unpack8(acc64, acc);

    float4 bb0 = __ldg((const float4*)(b2 + c * 8));
    float4 bb1 = __ldg((const float4*)(b2 + c * 8) + 1);
    float bv[8] = {bb0.x, bb0.y, bb0.z, bb0.w, bb1.x, bb1.y, bb1.z, bb1.w};
    float e[8];
#pragma unroll
    for (int j = 0; j < 8; j++) {
        e[j] = acc[j] * nd + bv[j];
        semb[ln][c * 8 + j] = fmaxf(e[j], 0.0f);
    }
    if (valid) {
        float4* eo = (float4*)(out_embed + (long)node * 32 + c * 8);
        eo[0] = make_float4(e[0], e[1], e[2], e[3]);
        eo[1] = make_float4(e[4], e[5], e[6], e[7]);
    }
    __syncthreads();

    float p[4] = {0.f, 0.f, 0.f, 0.f};
#pragma unroll 8
    for (int k = 0; k < 32; k++) {
        float a = semb[ln][k];
        float4 w = __ldg((const float4*)(W3 + k * 16 + c * 4));
        p[0] += a * w.x; p[1] += a * w.y; p[2] += a * w.z; p[3] += a * w.w;
    }
    if (valid) {
        __half2 h0 = __floats2half2_rn(p[0] * ns, p[1] * ns);
        __half2 h1v = __floats2half2_rn(p[2] * ns, p[3] * ns);
        uint2 u;
        u.x = *(unsigned*)&h0; u.y = *(unsigned*)&h1v;
        ((uint2*)(g_half + HOFF_P3))[node * 4 + c] = u;
    }
}

// ---------------- layer 3: gather(p3) + epilogue + reset state ----------------

__global__ void k_L3(const float* __restrict__ b3, float* __restrict__ out_h) {
    int t = blockIdx.x * blockDim.x + threadIdx.x;
    int n = t >> 1;
    int c = t & 1;
    if (n < NN) {
        unsigned long long acc64[4] = {0ULL, 0ULL, 0ULL, 0ULL};
        gather_row<2>(acc64, n, c, (const uint4*)(g_half + HOFF_P3));
        float acc[8];
        unpack8(acc64, acc);
        float nd = __ldg(&g_work[OFF_NDST + n]);
        float4 b0 = __ldg((const float4*)b3 + c * 2);
        float4 b1v = __ldg((const float4*)b3 + c * 2 + 1);
        float4* o = (float4*)(out_h + (long)n * 16 + c * 8);
        o[0] = make_float4(acc[0] * nd + b0.x, acc[1] * nd + b0.y,
                           acc[2] * nd + b0.z, acc[3] * nd + b0.w);
        o[1] = make_float4(acc[4] * nd + b1v.x, acc[5] * nd + b1v.y,
                           acc[6] * nd + b1v.z, acc[7] * nd + b1v.w);
    }
    // reset degree counters + scan flags for next call
    if (t < 2 * NN) g_int[t] = 0;
    if (t < 256) g_status[t] = 0ULL;
}

// ---------------- launch ----------------

extern "C" void kernel_launch(void* const* d_in, const int* in_sizes, int n_in,
                              void* d_out, int out_size) {
    const float* x  = (const float*)d_in[0];
    const float* W1 = (const float*)d_in[1];
    const float* b1 = (const float*)d_in[2];
    const float* W2 = (const float*)d_in[3];
    const float* b2 = (const float*)d_in[4];
    const float* W3 = (const float*)d_in[5];
    const float* b3 = (const float*)d_in[6];
    const int* src  = (const int*)d_in[7];
    const int* dst  = (const int*)d_in[8];
    float* out = (float*)d_out;
    int E = in_sizes[7];
    (void)n_in; (void)out_size;

    const int TB = 256;
    auto blk = [](long n, int tb) { return (int)((n + tb - 1) / tb); };

    k_deg<<<blk((E + 3) / 4, TB), TB>>>(src, dst, E);
    k_scan_norm<<<NB, 256>>>(x);
    k_fill<<<blk((E + 3) / 4, TB), TB>>>(src, dst, E);
    k_L1<<<blk(NN, 64), 256>>>(W1, b1, W2);
    k_L2<<<blk(NN, 64), 256>>>(W3, b2, out);
    k_L3<<<blk((long)NN * 2, TB), TB>>>(b3, out + 32 * NN);
}

// round 16
// speedup vs baseline: 1.5780x; 1.5780x over previous
#include <cuda_runtime.h>
#include <cuda_fp16.h>

#define NN 50000
#define NEMAX 1000000
#define NB 196          // ceil(NN/256)

// ---------------- scratch ----------------
__device__ __align__(256) float g_work[2 * NN];                 // [nsrc | ndst]
__device__ __align__(256) __half g_half[112 * NN];              // [y1 64NN | p2 32NN | p3 16NN]
// ints: [ideg NN | odeg NN | rowp NN+1 (+3 pad) | cur NN | csr NEMAX] ; csr 16B-aligned
__device__ __align__(256) int g_int[4 * NN + 4 + NEMAX];
__device__ __align__(256) unsigned long long g_status[256];     // lookback state (zero-init)

#define OFF_NSRC 0
#define OFF_NDST (NN)

#define HOFF_Y1 0
#define HOFF_P2 (64 * NN)
#define HOFF_P3 (96 * NN)

#define IOFF_IDEG 0
#define IOFF_ODEG (NN)
#define IOFF_ROWP (2 * NN)
#define IOFF_CUR  (3 * NN + 4)
#define IOFF_CSR  (4 * NN + 4)

// ---------------- degree ----------------

__global__ void k_deg(const int* __restrict__ src, const int* __restrict__ dst, int E) {
    int e = (blockIdx.x * blockDim.x + threadIdx.x) * 4;
    if (e + 3 < E) {
        int4 s = __ldg((const int4*)(src + e));
        int4 d = __ldg((const int4*)(dst + e));
        atomicAdd(&g_int[IOFF_ODEG + s.x], 1);
        atomicAdd(&g_int[IOFF_ODEG + s.y], 1);
        atomicAdd(&g_int[IOFF_ODEG + s.z], 1);
        atomicAdd(&g_int[IOFF_ODEG + s.w], 1);
        atomicAdd(&g_int[IOFF_IDEG + d.x], 1);
        atomicAdd(&g_int[IOFF_IDEG + d.y], 1);
        atomicAdd(&g_int[IOFF_IDEG + d.z], 1);
        atomicAdd(&g_int[IOFF_IDEG + d.w], 1);
    } else {
        for (int i = e; i < E; i++) {
            atomicAdd(&g_int[IOFF_ODEG + __ldg(src + i)], 1);
            atomicAdd(&g_int[IOFF_IDEG + __ldg(dst + i)], 1);
        }
    }
}

// ---------------- fused: norms + y1 scale + single-pass rowptr scan ------------

__global__ void k_scan_norm(const float* __restrict__ x) {
    __shared__ int sh[256];
    int t = threadIdx.x;
    int bid = blockIdx.x;
    int i = bid * 256 + t;

    int idv = 0, odv = 0;
    if (i < NN) {
        idv = g_int[IOFF_IDEG + i];
        odv = g_int[IOFF_ODEG + i];
    }
    float ns = rsqrtf(fmaxf((float)odv, 1.0f));
    float nd = rsqrtf(fmaxf((float)idv, 1.0f));
    if (i < NN) {
        g_work[OFF_NSRC + i] = ns;
        g_work[OFF_NDST + i] = nd;
    }

    sh[t] = idv;
    __syncthreads();
    for (int o = 1; o < 256; o <<= 1) {
        int v = (t >= o) ? sh[t - o] : 0;
        __syncthreads();
        sh[t] += v;
        __syncthreads();
    }
    int incl = sh[t];
    int total = sh[255];

    if (t == 0)
        atomicExch(&g_status[bid], (1ULL << 32) | (unsigned long long)(unsigned)total);

    if (i < NN) {
        const float4* px = (const float4*)(x + (long)i * 64);
        uint4* py = (uint4*)(g_half + HOFF_Y1) + i * 8;
#pragma unroll
        for (int q = 0; q < 8; q++) {
            float4 a = __ldg(px + q * 2);
            float4 b = __ldg(px + q * 2 + 1);
            __half2 h0 = __floats2half2_rn(a.x * ns, a.y * ns);
            __half2 h1 = __floats2half2_rn(a.z * ns, a.w * ns);
            __half2 h2 = __floats2half2_rn(b.x * ns, b.y * ns);
            __half2 h3 = __floats2half2_rn(b.z * ns, b.w * ns);
            uint4 u;
            u.x = *(unsigned*)&h0; u.y = *(unsigned*)&h1;
            u.z = *(unsigned*)&h2; u.w = *(unsigned*)&h3;
            py[q] = u;
        }
    }

    int myagg = 0;
    if (t < bid) {
        unsigned long long v;
        do { v = atomicOr(&g_status[t], 0ULL); } while ((v >> 32) == 0);
        myagg = (int)(v & 0xffffffffULL);
    }
    __syncthreads();
    sh[t] = myagg;
    __syncthreads();
    for (int o = 128; o > 0; o >>= 1) {
        if (t < o) sh[t] += sh[t + o];
        __syncthreads();
    }
    int blockpre = sh[0];

    int excl = blockpre + incl - idv;
    if (i < NN) {
        g_int[IOFF_ROWP + i] = excl;
        g_int[IOFF_CUR + i] = excl;
    }
    if (i == NN - 1) g_int[IOFF_ROWP + NN] = excl + idv;
}

__global__ void k_fill(const int* __restrict__ src, const int* __restrict__ dst, int E) {
    int e = (blockIdx.x * blockDim.x + threadIdx.x) * 4;
    if (e + 3 < E) {
        int4 s = __ldg((const int4*)(src + e));
        int4 d = __ldg((const int4*)(dst + e));
        g_int[IOFF_CSR + atomicAdd(&g_int[IOFF_CUR + d.x], 1)] = s.x;
        g_int[IOFF_CSR + atomicAdd(&g_int[IOFF_CUR + d.y], 1)] = s.y;
        g_int[IOFF_CSR + atomicAdd(&g_int[IOFF_CUR + d.z], 1)] = s.z;
        g_int[IOFF_CSR + atomicAdd(&g_int[IOFF_CUR + d.w], 1)] = s.w;
    } else {
        for (int i = e; i < E; i++) {
            int pos = atomicAdd(&g_int[IOFF_CUR + __ldg(dst + i)], 1);
            g_int[IOFF_CSR + pos] = __ldg(src + i);
        }
    }
}

// ---------------- packed fp32x2 accumulation helpers ----------------

__device__ __forceinline__ void acc_h2(unsigned long long& a, __half2 h) {
    float2 f = __half22float2(h);
    unsigned long long p;
    asm("mov.b64 %0, {%1, %2};" : "=l"(p) : "f"(f.x), "f"(f.y));
    asm("add.rn.f32x2 %0, %0, %1;" : "+l"(a) : "l"(p));
}

__device__ __forceinline__ void acc_pair(unsigned long long acc[4], uint4 a, uint4 b) {
    __half2 s0 = __hadd2(*(__half2*)&a.x, *(__half2*)&b.x);
    __half2 s1 = __hadd2(*(__half2*)&a.y, *(__half2*)&b.y);
    __half2 s2 = __hadd2(*(__half2*)&a.z, *(__half2*)&b.z);
    __half2 s3 = __hadd2(*(__half2*)&a.w, *(__half2*)&b.w);
    acc_h2(acc[0], s0); acc_h2(acc[1], s1); acc_h2(acc[2], s2); acc_h2(acc[3], s3);
}

__device__ __forceinline__ void acc_one(unsigned long long acc[4], uint4 u) {
    acc_h2(acc[0], *(__half2*)&u.x);
    acc_h2(acc[1], *(__half2*)&u.y);
    acc_h2(acc[2], *(__half2*)&u.z);
    acc_h2(acc[3], *(__half2*)&u.w);
}

__device__ __forceinline__ void unpack8(const unsigned long long acc[4], float o[8]) {
#pragma unroll
    for (int k = 0; k < 4; k++)
        asm("mov.b64 {%0, %1}, %2;" : "=f"(o[2 * k]), "=f"(o[2 * k + 1]) : "l"(acc[k]));
}

// gather: C lanes per node, 1 chunk per lane; int4 idx broadcast with
// software-pipelined index prefetch.
template <int C>
__device__ __forceinline__ void gather_row(unsigned long long acc[4], int n, int c,
                                           const uint4* __restrict__ msg) {
    int beg = __ldg(&g_int[IOFF_ROWP + n]);
    int end = __ldg(&g_int[IOFF_ROWP + n + 1]);
    int i = beg;
    while (i < end && (i & 3)) {
        acc_one(acc, msg[__ldg(&g_int[IOFF_CSR + i]) * C + c]);
        i++;
    }
    if (i + 7 < end) {
        int4 sa = __ldg((const int4*)&g_int[IOFF_CSR + i]);
        int4 sb = __ldg((const int4*)&g_int[IOFF_CSR + i + 4]);
        for (; i + 15 < end; i += 8) {
            int4 na = __ldg((const int4*)&g_int[IOFF_CSR + i + 8]);
            int4 nb = __ldg((const int4*)&g_int[IOFF_CSR + i + 12]);
            uint4 u0 = msg[sa.x * C + c];
            uint4 u1 = msg[sa.y * C + c];
            uint4 u2 = msg[sa.z * C + c];
            uint4 u3 = msg[sa.w * C + c];
            uint4 u4 = msg[sb.x * C + c];
            uint4 u5 = msg[sb.y * C + c];
            uint4 u6 = msg[sb.z * C + c];
            uint4 u7 = msg[sb.w * C + c];
            acc_pair(acc, u0, u1); acc_pair(acc, u2, u3);
            acc_pair(acc, u4, u5); acc_pair(acc, u6, u7);
            sa = na; sb = nb;
        }
        {
            uint4 u0 = msg[sa.x * C + c];
            uint4 u1 = msg[sa.y * C + c];
            uint4 u2 = msg[sa.z * C + c];
            uint4 u3 = msg[sa.w * C + c];
            uint4 u4 = msg[sb.x * C + c];
            uint4 u5 = msg[sb.y * C + c];
            uint4 u6 = msg[sb.z * C + c];
            uint4 u7 = msg[sb.w * C + c];
            acc_pair(acc, u0, u1); acc_pair(acc, u2, u3);
            acc_pair(acc, u4, u5); acc_pair(acc, u6, u7);
            i += 8;
        }
    }
    if (i + 3 < end) {
        int4 sa = __ldg((const int4*)&g_int[IOFF_CSR + i]);
        uint4 u0 = msg[sa.x * C + c];
        uint4 u1 = msg[sa.y * C + c];
        uint4 u2 = msg[sa.z * C + c];
        uint4 u3 = msg[sa.w * C + c];
        acc_pair(acc, u0, u1); acc_pair(acc, u2, u3);
        i += 4;
    }
    for (; i < end; i++)
        acc_one(acc, msg[__ldg(&g_int[IOFF_CSR + i]) * C + c]);
}

// layer-1 gather: 4 lanes/node, 2 consecutive chunks per lane, idx prefetch.
__device__ __forceinline__ void gather_row1(unsigned long long accA[4],
                                            unsigned long long accB[4],
                                            int n, int lane,
                                            const uint4* __restrict__ msg) {
    int beg = __ldg(&g_int[IOFF_ROWP + n]);
    int end = __ldg(&g_int[IOFF_ROWP + n + 1]);
    int i = beg;
    while (i < end && (i & 3)) {
        const uint4* m = msg + __ldg(&g_int[IOFF_CSR + i]) * 8 + lane * 2;
        acc_one(accA, m[0]);
        acc_one(accB, m[1]);
        i++;
    }
    if (i + 3 < end) {
        int4 sa = __ldg((const int4*)&g_int[IOFF_CSR + i]);
        for (; i + 7 < end; i += 4) {
            int4 na = __ldg((const int4*)&g_int[IOFF_CSR + i + 4]);
            const uint4* m0 = msg + sa.x * 8 + lane * 2;
            const uint4* m1 = msg + sa.y * 8 + lane * 2;
            const uint4* m2 = msg + sa.z * 8 + lane * 2;
            const uint4* m3 = msg + sa.w * 8 + lane * 2;
            uint4 a0 = m0[0], b0 = m0[1];
            uint4 a1 = m1[0], b1 = m1[1];
            uint4 a2 = m2[0], b2 = m2[1];
            uint4 a3 = m3[0], b3 = m3[1];
            acc_pair(accA, a0, a1); acc_pair(accB, b0, b1);
            acc_pair(accA, a2, a3); acc_pair(accB, b2, b3);
            sa = na;
        }
        {
            const uint4* m0 = msg + sa.x * 8 + lane * 2;
            const uint4* m1 = msg + sa.y * 8 + lane * 2;
            const uint4* m2 = msg + sa.z * 8 + lane * 2;
            const uint4* m3 = msg + sa.w * 8 + lane * 2;
            uint4 a0 = m0[0], b0 = m0[1];
            uint4 a1 = m1[0], b1 = m1[1];
            uint4 a2 = m2[0], b2 = m2[1];
            uint4 a3 = m3[0], b3 = m3[1];
            acc_pair(accA, a0, a1); acc_pair(accB, b0, b1);
            acc_pair(accA, a2, a3); acc_pair(accB, b2, b3);
            i += 4;
        }
    }
    for (; i < end; i++) {
        const uint4* m = msg + __ldg(&g_int[IOFF_CSR + i]) * 8 + lane * 2;
        acc_one(accA, m[0]);
        acc_one(accB, m[1]);
    }
}

// ---------------- fused layer 1: gather(y1) -> h1 -> p2(fp16) ----------------
// R13 config: 256 thr, 64-node tiles, launch_bounds(256,6).
// Gather: 4 lanes/node x 2 chunks. W1-MM: 4 nodes x 4 cols. p2-MM: 2 nodes (all thr).

__global__ void __launch_bounds__(256, 6)
k_L1(const float* __restrict__ W1, const float* __restrict__ b1,
     const float* __restrict__ W2) {
    __shared__ float sbuf[64][68];   // agg1, then reused for relu(h1)

    int t = threadIdx.x;
    {
        int lane = t & 3;
        int ln = t >> 2;             // 0..63
        int node = blockIdx.x * 64 + ln;
        unsigned long long accA[4] = {0ULL, 0ULL, 0ULL, 0ULL};
        unsigned long long accB[4] = {0ULL, 0ULL, 0ULL, 0ULL};
        float nd = 0.0f;
        if (node < NN) {
            gather_row1(accA, accB, node, lane, (const uint4*)(g_half + HOFF_Y1));
            nd = __ldg(&g_work[OFF_NDST + node]);
        }
        float a8[8];
        unpack8(accA, a8);
#pragma unroll
        for (int j = 0; j < 8; j++) sbuf[ln][lane * 16 + j] = a8[j] * nd;
        unpack8(accB, a8);
#pragma unroll
        for (int j = 0; j < 8; j++) sbuf[ln][lane * 16 + 8 + j] = a8[j] * nd;
    }
    __syncthreads();

    // W1-MM phase: cq = col chunk (4 cols of 64), q = node quad (4 nodes)
    int cq = t & 15;                 // 0..15
    int q = t >> 4;                  // 0..15
    int lnq = q * 4;

    float4 bb = __ldg((const float4*)(b1 + cq * 4));
    float h[4][4];
#pragma unroll
    for (int n = 0; n < 4; n++) {
        h[n][0] = bb.x; h[n][1] = bb.y; h[n][2] = bb.z; h[n][3] = bb.w;
    }
#pragma unroll 8
    for (int k = 0; k < 64; k++) {
        float4 w = __ldg((const float4*)(W1 + k * 64 + cq * 4));
        float a0 = sbuf[lnq + 0][k];
        float a1 = sbuf[lnq + 1][k];
        float a2 = sbuf[lnq + 2][k];
        float a3 = sbuf[lnq + 3][k];
        h[0][0] += a0 * w.x; h[0][1] += a0 * w.y; h[0][2] += a0 * w.z; h[0][3] += a0 * w.w;
        h[1][0] += a1 * w.x; h[1][1] += a1 * w.y; h[1][2] += a1 * w.z; h[1][3] += a1 * w.w;
        h[2][0] += a2 * w.x; h[2][1] += a2 * w.y; h[2][2] += a2 * w.z; h[2][3] += a2 * w.w;
        h[3][0] += a3 * w.x; h[3][1] += a3 * w.y; h[3][2] += a3 * w.z; h[3][3] += a3 * w.w;
    }
    __syncthreads();   // all reads of agg1 done -> reuse buffer
#pragma unroll
    for (int n = 0; n < 4; n++) {
#pragma unroll
        for (int j = 0; j < 4; j++)
            sbuf[lnq + n][cq * 4 + j] = fmaxf(h[n][j], 0.0f);
    }
    __syncthreads();

    // p2 = (h1 @ W2) * nsrc -> fp16 ; thread covers 4 cols x 2 nodes (all 256 thr)
    int c4 = t & 7;
    int pr = t >> 3;
    int ln0 = pr * 2, ln1 = pr * 2 + 1;
    int node0 = blockIdx.x * 64 + ln0;
    int node1 = node0 + 1;

    float p0[4] = {0.f, 0.f, 0.f, 0.f};
    float p1[4] = {0.f, 0.f, 0.f, 0.f};
#pragma unroll 8
    for (int k = 0; k < 64; k++) {
        float a0 = sbuf[ln0][k];
        float a1 = sbuf[ln1][k];
        float4 w = __ldg((const float4*)(W2 + k * 32 + c4 * 4));
        p0[0] += a0 * w.x; p0[1] += a0 * w.y; p0[2] += a0 * w.z; p0[3] += a0 * w.w;
        p1[0] += a1 * w.x; p1[1] += a1 * w.y; p1[2] += a1 * w.z; p1[3] += a1 * w.w;
    }
    if (node0 < NN) {
        float ns0 = __ldg(&g_work[OFF_NSRC + node0]);
        __half2 q0 = __floats2half2_rn(p0[0] * ns0, p0[1] * ns0);
        __half2 q1 = __floats2half2_rn(p0[2] * ns0, p0[3] * ns0);
        uint2 u;
        u.x = *(unsigned*)&q0; u.y = *(unsigned*)&q1;
        ((uint2*)(g_half + HOFF_P2))[node0 * 8 + c4] = u;
    }
    if (node1 < NN) {
        float ns1 = __ldg(&g_work[OFF_NSRC + node1]);
        __half2 q0 = __floats2half2_rn(p1[0] * ns1, p1[1] * ns1);
        __half2 q1 = __floats2half2_rn(p1[2] * ns1, p1[3] * ns1);
        uint2 u;
        u.x = *(unsigned*)&q0; u.y = *(unsigned*)&q1;
        ((uint2*)(g_half + HOFF_P2))[node1 * 8 + c4] = u;
    }
}

// ---------------- fused layer 2: gather(p2) -> embed(out) -> p3(fp16) --------
// 128 thr = 32 nodes x 4 chunks (grid 1563 for finer scheduling/occupancy).

__global__ void __launch_bounds__(128, 12)
k_L2(const float* __restrict__ W3, const float* __restrict__ b2,
     float* __restrict__ out_embed) {
    __shared__ float semb[32][36];

    int t = threadIdx.x;
    int ln = t >> 2;                 // 0..31
    int c = t & 3;
    int node = blockIdx.x * 32 + ln;
    bool valid = node < NN;

    unsigned long long acc64[4] = {0ULL, 0ULL, 0ULL, 0ULL};
    float nd = 0.0f, ns = 0.0f;
    if (valid) {
        gather_row<4>(acc64, node, c, (const uint4*)(g_half + HOFF_P2));
        nd = __ldg(&g_work[OFF_NDST + node]);
        ns = __ldg(&g_work[OFF_NSRC + node]);
    }
    float acc[8];
    unpack8(acc64, acc);

    float4 bb0 = __ldg((const float4*)(b2 + c * 8));
    float4 bb1 = __ldg((const float4*)(b2 + c * 8) + 1);
    float bv[8] = {bb0.x, bb0.y, bb0.z, bb0.w, bb1.x, bb1.y, bb1.z, bb1.w};
    float e[8];
#pragma unroll
    for (int j = 0; j < 8; j++) {
        e[j] = acc[j] * nd + bv[j];
        semb[ln][c * 8 + j] = fmaxf(e[j], 0.0f);
    }
    if (valid) {
        float4* eo = (float4*)(out_embed + (long)node * 32 + c * 8);
        eo[0] = make_float4(e[0], e[1], e[2], e[3]);
        eo[1] = make_float4(e[4], e[5], e[6], e[7]);
    }
    __syncthreads();

    float p[4] = {0.f, 0.f, 0.f, 0.f};
#pragma unroll 8
    for (int k = 0; k < 32; k++) {
        float a = semb[ln][k];
        float4 w = __ldg((const float4*)(W3 + k * 16 + c * 4));
        p[0] += a * w.x; p[1] += a * w.y; p[2] += a * w.z; p[3] += a * w.w;
    }
    if (valid) {
        __half2 h0 = __floats2half2_rn(p[0] * ns, p[1] * ns);
        __half2 h1v = __floats2half2_rn(p[2] * ns, p[3] * ns);
        uint2 u;
        u.x = *(unsigned*)&h0; u.y = *(unsigned*)&h1v;
        ((uint2*)(g_half + HOFF_P3))[node * 4 + c] = u;
    }
}

// ---------------- layer 3: gather(p3) + epilogue + reset state ----------------

__global__ void k_L3(const float* __restrict__ b3, float* __restrict__ out_h) {
    int t = blockIdx.x * blockDim.x + threadIdx.x;
    int n = t >> 1;
    int c = t & 1;
    if (n < NN) {
        unsigned long long acc64[4] = {0ULL, 0ULL, 0ULL, 0ULL};
        gather_row<2>(acc64, n, c, (const uint4*)(g_half + HOFF_P3));
        float acc[8];
        unpack8(acc64, acc);
        float nd = __ldg(&g_work[OFF_NDST + n]);
        float4 b0 = __ldg((const float4*)b3 + c * 2);
        float4 b1v = __ldg((const float4*)b3 + c * 2 + 1);
        float4* o = (float4*)(out_h + (long)n * 16 + c * 8);
        o[0] = make_float4(acc[0] * nd + b0.x, acc[1] * nd + b0.y,
                           acc[2] * nd + b0.z, acc[3] * nd + b0.w);
        o[1] = make_float4(acc[4] * nd + b1v.x, acc[5] * nd + b1v.y,
                           acc[6] * nd + b1v.z, acc[7] * nd + b1v.w);
    }
    // reset degree counters + scan flags for next call
    if (t < 2 * NN) g_int[t] = 0;
    if (t < 256) g_status[t] = 0ULL;
}

// ---------------- launch ----------------

extern "C" void kernel_launch(void* const* d_in, const int* in_sizes, int n_in,
                              void* d_out, int out_size) {
    const float* x  = (const float*)d_in[0];
    const float* W1 = (const float*)d_in[1];
    const float* b1 = (const float*)d_in[2];
    const float* W2 = (const float*)d_in[3];
    const float* b2 = (const float*)d_in[4];
    const float* W3 = (const float*)d_in[5];
    const float* b3 = (const float*)d_in[6];
    const int* src  = (const int*)d_in[7];
    const int* dst  = (const int*)d_in[8];
    float* out = (float*)d_out;
    int E = in_sizes[7];
    (void)n_in; (void)out_size;

    const int TB = 256;
    auto blk = [](long n, int tb) { return (int)((n + tb - 1) / tb); };

    k_deg<<<blk((E + 3) / 4, TB), TB>>>(src, dst, E);
    k_scan_norm<<<NB, 256>>>(x);
    k_fill<<<blk((E + 3) / 4, TB), TB>>>(src, dst, E);
    k_L1<<<blk(NN, 64), 256>>>(W1, b1, W2);
    k_L2<<<blk(NN, 32), 128>>>(W3, b2, out);
    k_L3<<<blk((long)NN * 2, TB), TB>>>(b3, out + 32 * NN);
}

// round 17
// speedup vs baseline: 1.6289x; 1.0322x over previous
#include <cuda_runtime.h>
#include <cuda_fp16.h>

#define NN 50000
#define NEMAX 1000000
#define NB 196          // ceil(NN/256)

// ---------------- scratch ----------------
__device__ __align__(256) float g_work[2 * NN];                 // [nsrc | ndst]
__device__ __align__(256) __half g_half[112 * NN];              // [y1 64NN | p2 32NN | p3 16NN]
// ints: [ideg NN | odeg NN | rowp NN+1 (+3 pad) | cur NN | csr NEMAX] ; csr 16B-aligned
__device__ __align__(256) int g_int[4 * NN + 4 + NEMAX];
__device__ __align__(256) unsigned long long g_status[256];     // lookback state (zero-init)

#define OFF_NSRC 0
#define OFF_NDST (NN)

#define HOFF_Y1 0
#define HOFF_P2 (64 * NN)
#define HOFF_P3 (96 * NN)

#define IOFF_IDEG 0
#define IOFF_ODEG (NN)
#define IOFF_ROWP (2 * NN)
#define IOFF_CUR  (3 * NN + 4)
#define IOFF_CSR  (4 * NN + 4)

// ---------------- degree ----------------

__global__ void k_deg(const int* __restrict__ src, const int* __restrict__ dst, int E) {
    int e = (blockIdx.x * blockDim.x + threadIdx.x) * 4;
    if (e + 3 < E) {
        int4 s = __ldg((const int4*)(src + e));
        int4 d = __ldg((const int4*)(dst + e));
        atomicAdd(&g_int[IOFF_ODEG + s.x], 1);
        atomicAdd(&g_int[IOFF_ODEG + s.y], 1);
        atomicAdd(&g_int[IOFF_ODEG + s.z], 1);
        atomicAdd(&g_int[IOFF_ODEG + s.w], 1);
        atomicAdd(&g_int[IOFF_IDEG + d.x], 1);
        atomicAdd(&g_int[IOFF_IDEG + d.y], 1);
        atomicAdd(&g_int[IOFF_IDEG + d.z], 1);
        atomicAdd(&g_int[IOFF_IDEG + d.w], 1);
    } else {
        for (int i = e; i < E; i++) {
            atomicAdd(&g_int[IOFF_ODEG + __ldg(src + i)], 1);
            atomicAdd(&g_int[IOFF_IDEG + __ldg(dst + i)], 1);
        }
    }
}

// ---------------- fused: norms + y1 scale + single-pass rowptr scan ------------

__global__ void k_scan_norm(const float* __restrict__ x) {
    __shared__ int sh[256];
    int t = threadIdx.x;
    int bid = blockIdx.x;
    int i = bid * 256 + t;

    int idv = 0, odv = 0;
    if (i < NN) {
        idv = g_int[IOFF_IDEG + i];
        odv = g_int[IOFF_ODEG + i];
    }
    float ns = rsqrtf(fmaxf((float)odv, 1.0f));
    float nd = rsqrtf(fmaxf((float)idv, 1.0f));
    if (i < NN) {
        g_work[OFF_NSRC + i] = ns;
        g_work[OFF_NDST + i] = nd;
    }

    sh[t] = idv;
    __syncthreads();
    for (int o = 1; o < 256; o <<= 1) {
        int v = (t >= o) ? sh[t - o] : 0;
        __syncthreads();
        sh[t] += v;
        __syncthreads();
    }
    int incl = sh[t];
    int total = sh[255];

    if (t == 0)
        atomicExch(&g_status[bid], (1ULL << 32) | (unsigned long long)(unsigned)total);

    if (i < NN) {
        const float4* px = (const float4*)(x + (long)i * 64);
        uint4* py = (uint4*)(g_half + HOFF_Y1) + i * 8;
#pragma unroll
        for (int q = 0; q < 8; q++) {
            float4 a = __ldg(px + q * 2);
            float4 b = __ldg(px + q * 2 + 1);
            __half2 h0 = __floats2half2_rn(a.x * ns, a.y * ns);
            __half2 h1 = __floats2half2_rn(a.z * ns, a.w * ns);
            __half2 h2 = __floats2half2_rn(b.x * ns, b.y * ns);
            __half2 h3 = __floats2half2_rn(b.z * ns, b.w * ns);
            uint4 u;
            u.x = *(unsigned*)&h0; u.y = *(unsigned*)&h1;
            u.z = *(unsigned*)&h2; u.w = *(unsigned*)&h3;
            py[q] = u;
        }
    }

    int myagg = 0;
    if (t < bid) {
        unsigned long long v;
        do { v = atomicOr(&g_status[t], 0ULL); } while ((v >> 32) == 0);
        myagg = (int)(v & 0xffffffffULL);
    }
    __syncthreads();
    sh[t] = myagg;
    __syncthreads();
    for (int o = 128; o > 0; o >>= 1) {
        if (t < o) sh[t] += sh[t + o];
        __syncthreads();
    }
    int blockpre = sh[0];

    int excl = blockpre + incl - idv;
    if (i < NN) {
        g_int[IOFF_ROWP + i] = excl;
        g_int[IOFF_CUR + i] = excl;
    }
    if (i == NN - 1) g_int[IOFF_ROWP + NN] = excl + idv;
}

__global__ void k_fill(const int* __restrict__ src, const int* __restrict__ dst, int E) {
    int e = (blockIdx.x * blockDim.x + threadIdx.x) * 4;
    if (e + 3 < E) {
        int4 s = __ldg((const int4*)(src + e));
        int4 d = __ldg((const int4*)(dst + e));
        g_int[IOFF_CSR + atomicAdd(&g_int[IOFF_CUR + d.x], 1)] = s.x;
        g_int[IOFF_CSR + atomicAdd(&g_int[IOFF_CUR + d.y], 1)] = s.y;
        g_int[IOFF_CSR + atomicAdd(&g_int[IOFF_CUR + d.z], 1)] = s.z;
        g_int[IOFF_CSR + atomicAdd(&g_int[IOFF_CUR + d.w], 1)] = s.w;
    } else {
        for (int i = e; i < E; i++) {
            int pos = atomicAdd(&g_int[IOFF_CUR + __ldg(dst + i)], 1);
            g_int[IOFF_CSR + pos] = __ldg(src + i);
        }
    }
}

// ---------------- packed fp32x2 accumulation helpers ----------------

__device__ __forceinline__ void acc_h2(unsigned long long& a, __half2 h) {
    float2 f = __half22float2(h);
    unsigned long long p;
    asm("mov.b64 %0, {%1, %2};" : "=l"(p) : "f"(f.x), "f"(f.y));
    asm("add.rn.f32x2 %0, %0, %1;" : "+l"(a) : "l"(p));
}

__device__ __forceinline__ void acc_pair(unsigned long long acc[4], uint4 a, uint4 b) {
    __half2 s0 = __hadd2(*(__half2*)&a.x, *(__half2*)&b.x);
    __half2 s1 = __hadd2(*(__half2*)&a.y, *(__half2*)&b.y);
    __half2 s2 = __hadd2(*(__half2*)&a.z, *(__half2*)&b.z);
    __half2 s3 = __hadd2(*(__half2*)&a.w, *(__half2*)&b.w);
    acc_h2(acc[0], s0); acc_h2(acc[1], s1); acc_h2(acc[2], s2); acc_h2(acc[3], s3);
}

__device__ __forceinline__ void acc_one(unsigned long long acc[4], uint4 u) {
    acc_h2(acc[0], *(__half2*)&u.x);
    acc_h2(acc[1], *(__half2*)&u.y);
    acc_h2(acc[2], *(__half2*)&u.z);
    acc_h2(acc[3], *(__half2*)&u.w);
}

__device__ __forceinline__ void unpack8(const unsigned long long acc[4], float o[8]) {
#pragma unroll
    for (int k = 0; k < 4; k++)
        asm("mov.b64 {%0, %1}, %2;" : "=f"(o[2 * k]), "=f"(o[2 * k + 1]) : "l"(acc[k]));
}

// gather: C lanes per node, 1 chunk per lane; int4 idx broadcast with
// software-pipelined index prefetch.
template <int C>
__device__ __forceinline__ void gather_row(unsigned long long acc[4], int n, int c,
                                           const uint4* __restrict__ msg) {
    int beg = __ldg(&g_int[IOFF_ROWP + n]);
    int end = __ldg(&g_int[IOFF_ROWP + n + 1]);
    int i = beg;
    while (i < end && (i & 3)) {
        acc_one(acc, msg[__ldg(&g_int[IOFF_CSR + i]) * C + c]);
        i++;
    }
    if (i + 7 < end) {
        int4 sa = __ldg((const int4*)&g_int[IOFF_CSR + i]);
        int4 sb = __ldg((const int4*)&g_int[IOFF_CSR + i + 4]);
        for (; i + 15 < end; i += 8) {
            int4 na = __ldg((const int4*)&g_int[IOFF_CSR + i + 8]);
            int4 nb = __ldg((const int4*)&g_int[IOFF_CSR + i + 12]);
            uint4 u0 = msg[sa.x * C + c];
            uint4 u1 = msg[sa.y * C + c];
            uint4 u2 = msg[sa.z * C + c];
            uint4 u3 = msg[sa.w * C + c];
            uint4 u4 = msg[sb.x * C + c];
            uint4 u5 = msg[sb.y * C + c];
            uint4 u6 = msg[sb.z * C + c];
            uint4 u7 = msg[sb.w * C + c];
            acc_pair(acc, u0, u1); acc_pair(acc, u2, u3);
            acc_pair(acc, u4, u5); acc_pair(acc, u6, u7);
            sa = na; sb = nb;
        }
        {
            uint4 u0 = msg[sa.x * C + c];
            uint4 u1 = msg[sa.y * C + c];
            uint4 u2 = msg[sa.z * C + c];
            uint4 u3 = msg[sa.w * C + c];
            uint4 u4 = msg[sb.x * C + c];
            uint4 u5 = msg[sb.y * C + c];
            uint4 u6 = msg[sb.z * C + c];
            uint4 u7 = msg[sb.w * C + c];
            acc_pair(acc, u0, u1); acc_pair(acc, u2, u3);
            acc_pair(acc, u4, u5); acc_pair(acc, u6, u7);
            i += 8;
        }
    }
    if (i + 3 < end) {
        int4 sa = __ldg((const int4*)&g_int[IOFF_CSR + i]);
        uint4 u0 = msg[sa.x * C + c];
        uint4 u1 = msg[sa.y * C + c];
        uint4 u2 = msg[sa.z * C + c];
        uint4 u3 = msg[sa.w * C + c];
        acc_pair(acc, u0, u1); acc_pair(acc, u2, u3);
        i += 4;
    }
    for (; i < end; i++)
        acc_one(acc, msg[__ldg(&g_int[IOFF_CSR + i]) * C + c]);
}

// layer-1 gather: 4 lanes/node, 2 consecutive chunks per lane, idx prefetch.
__device__ __forceinline__ void gather_row1(unsigned long long accA[4],
                                            unsigned long long accB[4],
                                            int n, int lane,
                                            const uint4* __restrict__ msg) {
    int beg = __ldg(&g_int[IOFF_ROWP + n]);
    int end = __ldg(&g_int[IOFF_ROWP + n + 1]);
    int i = beg;
    while (i < end && (i & 3)) {
        const uint4* m = msg + __ldg(&g_int[IOFF_CSR + i]) * 8 + lane * 2;
        acc_one(accA, m[0]);
        acc_one(accB, m[1]);
        i++;
    }
    if (i + 3 < end) {
        int4 sa = __ldg((const int4*)&g_int[IOFF_CSR + i]);
        for (; i + 7 < end; i += 4) {
            int4 na = __ldg((const int4*)&g_int[IOFF_CSR + i + 4]);
            const uint4* m0 = msg + sa.x * 8 + lane * 2;
            const uint4* m1 = msg + sa.y * 8 + lane * 2;
            const uint4* m2 = msg + sa.z * 8 + lane * 2;
            const uint4* m3 = msg + sa.w * 8 + lane * 2;
            uint4 a0 = m0[0], b0 = m0[1];
            uint4 a1 = m1[0], b1 = m1[1];
            uint4 a2 = m2[0], b2 = m2[1];
            uint4 a3 = m3[0], b3 = m3[1];
            acc_pair(accA, a0, a1); acc_pair(accB, b0, b1);
            acc_pair(accA, a2, a3); acc_pair(accB, b2, b3);
            sa = na;
        }
        {
            const uint4* m0 = msg + sa.x * 8 + lane * 2;
            const uint4* m1 = msg + sa.y * 8 + lane * 2;
            const uint4* m2 = msg + sa.z * 8 + lane * 2;
            const uint4* m3 = msg + sa.w * 8 + lane * 2;
            uint4 a0 = m0[0], b0 = m0[1];
            uint4 a1 = m1[0], b1 = m1[1];
            uint4 a2 = m2[0], b2 = m2[1];
            uint4 a3 = m3[0], b3 = m3[1];
            acc_pair(accA, a0, a1); acc_pair(accB, b0, b1);
            acc_pair(accA, a2, a3); acc_pair(accB, b2, b3);
            i += 4;
        }
    }
    for (; i < end; i++) {
        const uint4* m = msg + __ldg(&g_int[IOFF_CSR + i]) * 8 + lane * 2;
        acc_one(accA, m[0]);
        acc_one(accB, m[1]);
    }
}

// ---------------- fused layer 1: gather(y1) -> h1 -> p2(fp16) ----------------
// 128 thr, 32-node tiles (halved straggler coupling, finer grid balance).
// Gather: 4 lanes/node x 2 chunks. W1-MM: 4 nodes x 4 cols (16cq x 8q).
// p2-MM: 2 nodes x 4 cols (8c4 x 16pr). All phases use all 128 threads.

__global__ void __launch_bounds__(128, 12)
k_L1(const float* __restrict__ W1, const float* __restrict__ b1,
     const float* __restrict__ W2) {
    __shared__ float sbuf[32][68];   // agg1, then reused for relu(h1)

    int t = threadIdx.x;
    {
        int lane = t & 3;
        int ln = t >> 2;             // 0..31
        int node = blockIdx.x * 32 + ln;
        unsigned long long accA[4] = {0ULL, 0ULL, 0ULL, 0ULL};
        unsigned long long accB[4] = {0ULL, 0ULL, 0ULL, 0ULL};
        float nd = 0.0f;
        if (node < NN) {
            gather_row1(accA, accB, node, lane, (const uint4*)(g_half + HOFF_Y1));
            nd = __ldg(&g_work[OFF_NDST + node]);
        }
        float a8[8];
        unpack8(accA, a8);
#pragma unroll
        for (int j = 0; j < 8; j++) sbuf[ln][lane * 16 + j] = a8[j] * nd;
        unpack8(accB, a8);
#pragma unroll
        for (int j = 0; j < 8; j++) sbuf[ln][lane * 16 + 8 + j] = a8[j] * nd;
    }
    __syncthreads();

    // W1-MM phase: cq = col chunk (4 cols of 64), q = node quad (4 nodes)
    int cq = t & 15;                 // 0..15
    int q = t >> 4;                  // 0..7
    int lnq = q * 4;

    float4 bb = __ldg((const float4*)(b1 + cq * 4));
    float h[4][4];
#pragma unroll
    for (int n = 0; n < 4; n++) {
        h[n][0] = bb.x; h[n][1] = bb.y; h[n][2] = bb.z; h[n][3] = bb.w;
    }
#pragma unroll 8
    for (int k = 0; k < 64; k++) {
        float4 w = __ldg((const float4*)(W1 + k * 64 + cq * 4));
        float a0 = sbuf[lnq + 0][k];
        float a1 = sbuf[lnq + 1][k];
        float a2 = sbuf[lnq + 2][k];
        float a3 = sbuf[lnq + 3][k];
        h[0][0] += a0 * w.x; h[0][1] += a0 * w.y; h[0][2] += a0 * w.z; h[0][3] += a0 * w.w;
        h[1][0] += a1 * w.x; h[1][1] += a1 * w.y; h[1][2] += a1 * w.z; h[1][3] += a1 * w.w;
        h[2][0] += a2 * w.x; h[2][1] += a2 * w.y; h[2][2] += a2 * w.z; h[2][3] += a2 * w.w;
        h[3][0] += a3 * w.x; h[3][1] += a3 * w.y; h[3][2] += a3 * w.z; h[3][3] += a3 * w.w;
    }
    __syncthreads();   // all reads of agg1 done -> reuse buffer
#pragma unroll
    for (int n = 0; n < 4; n++) {
#pragma unroll
        for (int j = 0; j < 4; j++)
            sbuf[lnq + n][cq * 4 + j] = fmaxf(h[n][j], 0.0f);
    }
    __syncthreads();

    // p2 = (h1 @ W2) * nsrc -> fp16 ; thread covers 4 cols x 2 nodes
    int c4 = t & 7;
    int pr = t >> 3;                 // 0..15
    int ln0 = pr * 2, ln1 = pr * 2 + 1;
    int node0 = blockIdx.x * 32 + ln0;
    int node1 = node0 + 1;

    float p0[4] = {0.f, 0.f, 0.f, 0.f};
    float p1[4] = {0.f, 0.f, 0.f, 0.f};
#pragma unroll 8
    for (int k = 0; k < 64; k++) {
        float a0 = sbuf[ln0][k];
        float a1 = sbuf[ln1][k];
        float4 w = __ldg((const float4*)(W2 + k * 32 + c4 * 4));
        p0[0] += a0 * w.x; p0[1] += a0 * w.y; p0[2] += a0 * w.z; p0[3] += a0 * w.w;
        p1[0] += a1 * w.x; p1[1] += a1 * w.y; p1[2] += a1 * w.z; p1[3] += a1 * w.w;
    }
    if (node0 < NN) {
        float ns0 = __ldg(&g_work[OFF_NSRC + node0]);
        __half2 q0 = __floats2half2_rn(p0[0] * ns0, p0[1] * ns0);
        __half2 q1 = __floats2half2_rn(p0[2] * ns0, p0[3] * ns0);
        uint2 u;
        u.x = *(unsigned*)&q0; u.y = *(unsigned*)&q1;
        ((uint2*)(g_half + HOFF_P2))[node0 * 8 + c4] = u;
    }
    if (node1 < NN) {
        float ns1 = __ldg(&g_work[OFF_NSRC + node1]);
        __half2 q0 = __floats2half2_rn(p1[0] * ns1, p1[1] * ns1);
        __half2 q1 = __floats2half2_rn(p1[2] * ns1, p1[3] * ns1);
        uint2 u;
        u.x = *(unsigned*)&q0; u.y = *(unsigned*)&q1;
        ((uint2*)(g_half + HOFF_P2))[node1 * 8 + c4] = u;
    }
}

// ---------------- fused layer 2: gather(p2) -> embed(out) -> p3(fp16) --------
// 128 thr = 32 nodes x 4 chunks.

__global__ void __launch_bounds__(128, 12)
k_L2(const float* __restrict__ W3, const float* __restrict__ b2,
     float* __restrict__ out_embed) {
    __shared__ float semb[32][36];

    int t = threadIdx.x;
    int ln = t >> 2;                 // 0..31
    int c = t & 3;
    int node = blockIdx.x * 32 + ln;
    bool valid = node < NN;

    unsigned long long acc64[4] = {0ULL, 0ULL, 0ULL, 0ULL};
    float nd = 0.0f, ns = 0.0f;
    if (valid) {
        gather_row<4>(acc64, node, c, (const uint4*)(g_half + HOFF_P2));
        nd = __ldg(&g_work[OFF_NDST + node]);
        ns = __ldg(&g_work[OFF_NSRC + node]);
    }
    float acc[8];
    unpack8(acc64, acc);

    float4 bb0 = __ldg((const float4*)(b2 + c * 8));
    float4 bb1 = __ldg((const float4*)(b2 + c * 8) + 1);
    float bv[8] = {bb0.x, bb0.y, bb0.z, bb0.w, bb1.x, bb1.y, bb1.z, bb1.w};
    float e[8];
#pragma unroll
    for (int j = 0; j < 8; j++) {
        e[j] = acc[j] * nd + bv[j];
        semb[ln][c * 8 + j] = fmaxf(e[j], 0.0f);
    }
    if (valid) {
        float4* eo = (float4*)(out_embed + (long)node * 32 + c * 8);
        eo[0] = make_float4(e[0], e[1], e[2], e[3]);
        eo[1] = make_float4(e[4], e[5], e[6], e[7]);
    }
    __syncthreads();

    float p[4] = {0.f, 0.f, 0.f, 0.f};
#pragma unroll 8
    for (int k = 0; k < 32; k++) {
        float a = semb[ln][k];
        float4 w = __ldg((const float4*)(W3 + k * 16 + c * 4));
        p[0] += a * w.x; p[1] += a * w.y; p[2] += a * w.z; p[3] += a * w.w;
    }
    if (valid) {
        __half2 h0 = __floats2half2_rn(p[0] * ns, p[1] * ns);
        __half2 h1v = __floats2half2_rn(p[2] * ns, p[3] * ns);
        uint2 u;
        u.x = *(unsigned*)&h0; u.y = *(unsigned*)&h1v;
        ((uint2*)(g_half + HOFF_P3))[node * 4 + c] = u;
    }
}

// ---------------- layer 3: gather(p3) + epilogue + reset state ----------------

__global__ void k_L3(const float* __restrict__ b3, float* __restrict__ out_h) {
    int t = blockIdx.x * blockDim.x + threadIdx.x;
    int n = t >> 1;
    int c = t & 1;
    if (n < NN) {
        unsigned long long acc64[4] = {0ULL, 0ULL, 0ULL, 0ULL};
        gather_row<2>(acc64, n, c, (const uint4*)(g_half + HOFF_P3));
        float acc[8];
        unpack8(acc64, acc);
        float nd = __ldg(&g_work[OFF_NDST + n]);
        float4 b0 = __ldg((const float4*)b3 + c * 2);
        float4 b1v = __ldg((const float4*)b3 + c * 2 + 1);
        float4* o = (float4*)(out_h + (long)n * 16 + c * 8);
        o[0] = make_float4(acc[0] * nd + b0.x, acc[1] * nd + b0.y,
                           acc[2] * nd + b0.z, acc[3] * nd + b0.w);
        o[1] = make_float4(acc[4] * nd + b1v.x, acc[5] * nd + b1v.y,
                           acc[6] * nd + b1v.z, acc[7] * nd + b1v.w);
    }
    // reset degree counters + scan flags for next call
    if (t < 2 * NN) g_int[t] = 0;
    if (t < 256) g_status[t] = 0ULL;
}

// ---------------- launch ----------------

extern "C" void kernel_launch(void* const* d_in, const int* in_sizes, int n_in,
                              void* d_out, int out_size) {
    const float* x  = (const float*)d_in[0];
    const float* W1 = (const float*)d_in[1];
    const float* b1 = (const float*)d_in[2];
    const float* W2 = (const float*)d_in[3];
    const float* b2 = (const float*)d_in[4];
    const float* W3 = (const float*)d_in[5];
    const float* b3 = (const float*)d_in[6];
    const int* src  = (const int*)d_in[7];
    const int* dst  = (const int*)d_in[8];
    float* out = (float*)d_out;
    int E = in_sizes[7];
    (void)n_in; (void)out_size;

    const int TB = 256;
    auto blk = [](long n, int tb) { return (int)((n + tb - 1) / tb); };

    k_deg<<<blk((E + 3) / 4, TB), TB>>>(src, dst, E);
    k_scan_norm<<<NB, 256>>>(x);
    k_fill<<<blk((E + 3) / 4, TB), TB>>>(src, dst, E);
    k_L1<<<blk(NN, 32), 128>>>(W1, b1, W2);
    k_L2<<<blk(NN, 32), 128>>>(W3, b2, out);
    k_L3<<<blk((long)NN * 2, TB), TB>>>(b3, out + 32 * NN);
}